// round 8
// baseline (speedup 1.0000x reference)
#include <cuda_runtime.h>
#include <math.h>
#include <stdint.h>

#define NMAX 262144
#define EMAX 4194304
#define NBANK 16
#define BSTRIDE 32   // doubles per bank (256B stride: no L2 hash pair-collide)

// ---------------- scratch (device globals; single zero-memset of g) ----------
struct ScratchT {
    float    h1[4 * NMAX];            // conv1 accum: h0, h1, cnt, pad
    float    h2[4 * NMAX];            // conv2 accum: 4 channels
    double   stats1[NBANK * BSTRIDE]; // banked: [b]: s0,s1,sq0,sq1
    double   stats2[NBANK * BSTRIDE]; // banked: [b]: s0..s3, sq0..sq3
    unsigned done1, done2;            // last-block counters
    unsigned pool[64];                // sign-aware ordered-uint, 0 == empty
};
__device__ ScratchT g;
__device__ int2     g_pair[EMAX];     // conv1-packed {src,dst} int32 (no memset)
__device__ float    g_h1e[2 * NMAX];  // elu(mean(h1)) packed float2
__device__ float    g_inv[NMAX];      // 1 / max(cnt,1)
__device__ float    g_scale1[2], g_shift1[2];
__device__ float    g_scale2[4], g_shift2[4];

// ordered-uint encoding: unsigned compare == float compare
__device__ __forceinline__ unsigned fenc(float f) {
    unsigned u = __float_as_uint(f);
    return (u & 0x80000000u) ? ~u : (u | 0x80000000u);
}
__device__ __forceinline__ float fdec(unsigned u) {
    return (u & 0x80000000u) ? __uint_as_float(u & 0x7FFFFFFFu)
                             : __uint_as_float(~u);
}
#define REBASE 0x007FFFFFu   // fenc(-inf): re-base so 0 marks "empty"

// ---------------- trilinear basis weights (pseudo in [0,1): lo==0) -----------
__device__ __forceinline__ void basis8(float f0, float f1, float f2, float* w) {
    float gr0 = 1.f - f0, gr1 = 1.f - f1, gr2 = 1.f - f2;
    float a00 = gr0 * gr1, a10 = f0 * gr1, a01 = gr0 * f1, a11 = f0 * f1;
    w[0] = a00 * gr2; w[1] = a10 * gr2; w[2] = a01 * gr2; w[3] = a11 * gr2;
    w[4] = a00 * f2;  w[5] = a10 * f2;  w[6] = a01 * f2;  w[7] = a11 * f2;
}

// per-block idx-dtype sniff: odd 32-bit words all zero over 8 samples => int64
__device__ __forceinline__ int sniff64(const unsigned* w, int base, int E) {
    unsigned orv = 0;
#pragma unroll
    for (int i = 0; i < 8; i++) {
        int e = base + i;
        if (e < E) orv |= w[2 * e + 1];
    }
    return orv == 0u;
}

__device__ __forceinline__ void load_edge2(const void* eidx, int e, int E, int is64,
                                           int& sA, int& dA, int& sB, int& dB) {
    if (is64) {
        const longlong2* p = (const longlong2*)eidx;
        longlong2 s = __ldg(&p[e >> 1]);
        longlong2 d = __ldg(&p[(size_t)(E >> 1) + (e >> 1)]);
        sA = (int)s.x; sB = (int)s.y; dA = (int)d.x; dB = (int)d.y;
    } else {
        const int2* p = (const int2*)eidx;
        int2 s = __ldg(&p[e >> 1]);
        int2 d = __ldg(&p[(E >> 1) + (e >> 1)]);
        sA = s.x; sB = s.y; dA = d.x; dB = d.y;
    }
}
__device__ __forceinline__ void load_edge1(const void* eidx, int e, int E, int is64,
                                           int& src, int& dst) {
    if (is64) {
        const long long* p = (const long long*)eidx;
        src = (int)__ldg(&p[e]);
        dst = (int)__ldg(&p[(size_t)E + e]);
    } else {
        const int* p = (const int*)eidx;
        src = __ldg(&p[e]);
        dst = __ldg(&p[E + e]);
    }
}

// stage 512 edges' attr (1536 floats) into smem via coalesced float4 loads
__device__ __forceinline__ void stage_attr512(const float* __restrict__ attr,
                                              int base, int nEdge, float* sAttr) {
    int t = threadIdx.x;
    if (nEdge == 512) {
        const float4* a4 = (const float4*)attr;
        int g0 = (3 * base) >> 2;
#pragma unroll
        for (int i = 0; i < 2; i++) {
            int k = t + 256 * i;
            if (k < 384) *(float4*)&sAttr[4 * k] = __ldg(&a4[g0 + k]);
        }
    } else {
        for (int i = t; i < 3 * nEdge; i += 256)
            sAttr[i] = __ldg(&attr[3 * base + i]);
    }
    __syncthreads();
}

// ---- conv1: x[N,1] x W1 -> red.v4 (h0,h1,cnt,0); packs {src,dst} int32 ------
__global__ void __launch_bounds__(256) k_conv1(
        const float* __restrict__ x, const void* __restrict__ eidx,
        const float* __restrict__ attr, const float* __restrict__ W1, int E) {
    __shared__ float2 sW[8];
    __shared__ float  sAttr[1536];
    __shared__ int    sI64;
    int t = threadIdx.x;
    int base = blockIdx.x * 512;
    if (t < 8) sW[t] = ((const float2*)W1)[t];
    if (t == 0) sI64 = sniff64((const unsigned*)eidx, base, E);
    int nEdge = min(512, E - base);
    stage_attr512(attr, base, nEdge, sAttr);

    int le = 2 * t;
    if (le >= nEdge) return;
    int e = base + le;

    if (le + 1 < nEdge) {
        int sA, dA, sB, dB;
        load_edge2(eidx, e, E, sI64, sA, dA, sB, dB);
        *(int4*)&g_pair[e] = make_int4(sA, dA, sB, dB);   // repack for conv2
        float xA = __ldg(&x[sA]);
        float xB = __ldg(&x[sB]);
        float w[8];
        basis8(sAttr[3*le], sAttr[3*le+1], sAttr[3*le+2], w);
        float a0 = 0.f, a1 = 0.f;
#pragma unroll
        for (int b = 0; b < 8; b++) { float2 W = sW[b]; a0 = fmaf(w[b], W.x, a0); a1 = fmaf(w[b], W.y, a1); }
        a0 *= xA; a1 *= xA;
        asm volatile("red.global.add.v4.f32 [%0], {%1, %2, %3, %4};"
                     :: "l"(&g.h1[4 * dA]), "f"(a0), "f"(a1), "f"(1.0f), "f"(0.0f) : "memory");
        basis8(sAttr[3*le+3], sAttr[3*le+4], sAttr[3*le+5], w);
        float b0 = 0.f, b1 = 0.f;
#pragma unroll
        for (int b = 0; b < 8; b++) { float2 W = sW[b]; b0 = fmaf(w[b], W.x, b0); b1 = fmaf(w[b], W.y, b1); }
        b0 *= xB; b1 *= xB;
        asm volatile("red.global.add.v4.f32 [%0], {%1, %2, %3, %4};"
                     :: "l"(&g.h1[4 * dB]), "f"(b0), "f"(b1), "f"(1.0f), "f"(0.0f) : "memory");
    } else {
        int src, dst;
        load_edge1(eidx, e, E, sI64, src, dst);
        g_pair[e] = make_int2(src, dst);
        float w[8];
        basis8(sAttr[3*le], sAttr[3*le+1], sAttr[3*le+2], w);
        float a0 = 0.f, a1 = 0.f;
#pragma unroll
        for (int b = 0; b < 8; b++) { float2 W = sW[b]; a0 = fmaf(w[b], W.x, a0); a1 = fmaf(w[b], W.y, a1); }
        float xs = __ldg(&x[src]);
        a0 *= xs; a1 *= xs;
        asm volatile("red.global.add.v4.f32 [%0], {%1, %2, %3, %4};"
                     :: "l"(&g.h1[4 * dst]), "f"(a0), "f"(a1), "f"(1.0f), "f"(0.0f) : "memory");
    }
}

// ---------------- finish1: 4 nodes/thread, mean->ELU->store, BN1 stats -------
__global__ void __launch_bounds__(256) k_finish1(
        const float* __restrict__ gamma1, const float* __restrict__ beta1, int N) {
    __shared__ float wsum[8][4];
    int t = threadIdx.x;
    int base = blockIdx.x * 1024;
    float s0 = 0.f, s1 = 0.f, s2 = 0.f, s3 = 0.f;
#pragma unroll
    for (int k = 0; k < 4; k++) {
        int n = base + t + 256 * k;
        if (n < N) {
            float4 h  = *(const float4*)&g.h1[4 * n];
            float inv = 1.0f / fmaxf(h.z, 1.0f);
            g_inv[n] = inv;
            float a = h.x * inv, b = h.y * inv;
            a = (a > 0.f) ? a : expm1f(a);
            b = (b > 0.f) ? b : expm1f(b);
            *(float2*)&g_h1e[2 * n] = make_float2(a, b);
            s0 += a; s1 += b; s2 += a * a; s3 += b * b;
        }
    }
#pragma unroll
    for (int o = 16; o; o >>= 1) {
        s0 += __shfl_down_sync(~0u, s0, o);
        s1 += __shfl_down_sync(~0u, s1, o);
        s2 += __shfl_down_sync(~0u, s2, o);
        s3 += __shfl_down_sync(~0u, s3, o);
    }
    if ((t & 31) == 0) {
        int wid = t >> 5;
        wsum[wid][0] = s0; wsum[wid][1] = s1; wsum[wid][2] = s2; wsum[wid][3] = s3;
    }
    __syncthreads();
    if (t < 4) {
        double acc = 0.0;
#pragma unroll
        for (int w = 0; w < 8; w++) acc += (double)wsum[w][t];
        atomicAdd(&g.stats1[(blockIdx.x & (NBANK - 1)) * BSTRIDE + t], acc);
    }
    __shared__ int last;
    __syncthreads();
    if (t == 0) {
        __threadfence();
        last = (atomicAdd(&g.done1, 1u) == gridDim.x - 1);
    }
    __syncthreads();
    if (last && t < 2) {
        __threadfence();
        double sum = 0.0, sumsq = 0.0;
#pragma unroll
        for (int bk = 0; bk < NBANK; bk++) {
            sum   += g.stats1[bk * BSTRIDE + t];
            sumsq += g.stats1[bk * BSTRIDE + 2 + t];
        }
        double invN = 1.0 / (double)N;
        double mu   = sum * invN;
        double var  = sumsq * invN - mu * mu;
        float  sc   = (float)((double)gamma1[t] / sqrt(var + 1e-5));
        g_scale1[t] = sc;
        g_shift1[t] = beta1[t] - (float)mu * sc;
    }
}

// ---- conv2: BN1(h1e)[N,2] x W2 -> red.v4 [N,4]; packed-int2 indices ---------
__global__ void __launch_bounds__(256) k_conv2(
        const float* __restrict__ attr, const float* __restrict__ W2, int E) {
    __shared__ float4 sW[16];
    __shared__ float  sAttr[1536];
    __shared__ float  sSc[2], sSh[2];
    int t = threadIdx.x;
    int base = blockIdx.x * 512;
    if (t < 16) sW[t] = ((const float4*)W2)[t];
    if (t < 2)  { sSc[t] = g_scale1[t]; sSh[t] = g_shift1[t]; }
    int nEdge = min(512, E - base);
    stage_attr512(attr, base, nEdge, sAttr);

    int le = 2 * t;
    if (le >= nEdge) return;
    int e = base + le;

    if (le + 1 < nEdge) {
        int4 P = __ldg((const int4*)&g_pair[e]);      // {sA,dA,sB,dB}, one LDG.128
        float2 hA = *(const float2*)&g_h1e[2 * P.x];  // both gathers in flight
        float2 hB = *(const float2*)&g_h1e[2 * P.z];
        float w[8];
#pragma unroll
        for (int j = 0; j < 2; j++) {
            float2 hv = j ? hB : hA;
            int    d  = j ? P.w : P.y;
            float h0 = fmaf(hv.x, sSc[0], sSh[0]);
            float h1 = fmaf(hv.y, sSc[1], sSh[1]);
            basis8(sAttr[3*(le+j)], sAttr[3*(le+j)+1], sAttr[3*(le+j)+2], w);
            float acc0 = 0.f, acc1 = 0.f, acc2 = 0.f, acc3 = 0.f;
#pragma unroll
            for (int b = 0; b < 8; b++) {
                float4 A = sW[2 * b];
                float4 B = sW[2 * b + 1];
                float wb = w[b];
                acc0 = fmaf(wb, fmaf(h1, B.x, h0 * A.x), acc0);
                acc1 = fmaf(wb, fmaf(h1, B.y, h0 * A.y), acc1);
                acc2 = fmaf(wb, fmaf(h1, B.z, h0 * A.z), acc2);
                acc3 = fmaf(wb, fmaf(h1, B.w, h0 * A.w), acc3);
            }
            asm volatile("red.global.add.v4.f32 [%0], {%1, %2, %3, %4};"
                         :: "l"(&g.h2[4 * d]), "f"(acc0), "f"(acc1), "f"(acc2), "f"(acc3)
                         : "memory");
        }
    } else {
        int2 P = __ldg(&g_pair[e]);
        float2 hv = *(const float2*)&g_h1e[2 * P.x];
        float h0 = fmaf(hv.x, sSc[0], sSh[0]);
        float h1 = fmaf(hv.y, sSc[1], sSh[1]);
        float w[8];
        basis8(sAttr[3*le], sAttr[3*le+1], sAttr[3*le+2], w);
        float acc0 = 0.f, acc1 = 0.f, acc2 = 0.f, acc3 = 0.f;
#pragma unroll
        for (int b = 0; b < 8; b++) {
            float4 A = sW[2 * b];
            float4 B = sW[2 * b + 1];
            float wb = w[b];
            acc0 = fmaf(wb, fmaf(h1, B.x, h0 * A.x), acc0);
            acc1 = fmaf(wb, fmaf(h1, B.y, h0 * A.y), acc1);
            acc2 = fmaf(wb, fmaf(h1, B.z, h0 * A.z), acc2);
            acc3 = fmaf(wb, fmaf(h1, B.w, h0 * A.w), acc3);
        }
        asm volatile("red.global.add.v4.f32 [%0], {%1, %2, %3, %4};"
                     :: "l"(&g.h2[4 * P.y]), "f"(acc0), "f"(acc1), "f"(acc2), "f"(acc3)
                     : "memory");
    }
}

// -- finish2: 4 nodes/thread; mean, BN2 stats+params, sign-aware pool, fc -----
__global__ void __launch_bounds__(256) k_finish2(
        const float* __restrict__ pos,
        const float* __restrict__ gamma2, const float* __restrict__ beta2,
        const float* __restrict__ fcw, float* __restrict__ out, int N) {
    __shared__ unsigned spool[64];
    __shared__ float    wsum[8][8];
    __shared__ unsigned sNeg;
    int t = threadIdx.x;
    if (t < 64) spool[t] = 0u;
    if (t == 0) {
        unsigned mk = 0;
#pragma unroll
        for (int o = 0; o < 4; o++)
            if (__ldg(&gamma2[o]) < 0.f) mk |= 1u << o;
        sNeg = mk;
    }
    __syncthreads();
    unsigned neg = sNeg;

    int base = blockIdx.x * 1024;
    float s[8] = {0.f,0.f,0.f,0.f,0.f,0.f,0.f,0.f};
#pragma unroll
    for (int k = 0; k < 4; k++) {
        int n = base + t + 256 * k;
        if (n < N) {
            float4 h  = *(const float4*)&g.h2[4 * n];
            float inv = g_inv[n];
            float m0 = h.x * inv, m1 = h.y * inv, m2 = h.z * inv, m3 = h.w * inv;
            float2 p = *(const float2*)&pos[2 * n];
            int cx = min(max((int)floorf(p.x * 0.04f), 0), 3);
            int cy = min(max((int)floorf(p.y * 0.04f), 0), 3);
            int cl = 4 * (cx + 4 * cy);
            unsigned e0 = fenc(m0), e1 = fenc(m1), e2 = fenc(m2), e3 = fenc(m3);
            atomicMax(&spool[cl + 0], (neg & 1u) ? ~e0 : (e0 - REBASE));
            atomicMax(&spool[cl + 1], (neg & 2u) ? ~e1 : (e1 - REBASE));
            atomicMax(&spool[cl + 2], (neg & 4u) ? ~e2 : (e2 - REBASE));
            atomicMax(&spool[cl + 3], (neg & 8u) ? ~e3 : (e3 - REBASE));
            s[0] += m0; s[1] += m1; s[2] += m2; s[3] += m3;
            s[4] += m0 * m0; s[5] += m1 * m1; s[6] += m2 * m2; s[7] += m3 * m3;
        }
    }
#pragma unroll
    for (int o = 16; o; o >>= 1)
#pragma unroll
        for (int k = 0; k < 8; k++) s[k] += __shfl_down_sync(~0u, s[k], o);
    if ((t & 31) == 0) {
        int wid = t >> 5;
#pragma unroll
        for (int k = 0; k < 8; k++) wsum[wid][k] = s[k];
    }
    __syncthreads();
    if (t < 8) {
        double acc = 0.0;
#pragma unroll
        for (int w = 0; w < 8; w++) acc += (double)wsum[w][t];
        atomicAdd(&g.stats2[(blockIdx.x & (NBANK - 1)) * BSTRIDE + t], acc);
    }
    if (t < 64 && spool[t]) atomicMax(&g.pool[t], spool[t]);
    __shared__ int last;
    __syncthreads();
    if (t == 0) {
        __threadfence();
        last = (atomicAdd(&g.done2, 1u) == gridDim.x - 1);
    }
    __syncthreads();
    if (!last) return;

    if (t < 4) {
        __threadfence();
        double sum = 0.0, sumsq = 0.0;
#pragma unroll
        for (int bk = 0; bk < NBANK; bk++) {
            sum   += g.stats2[bk * BSTRIDE + t];
            sumsq += g.stats2[bk * BSTRIDE + 4 + t];
        }
        double invN = 1.0 / (double)N;
        double mu   = sum * invN;
        double var  = sumsq * invN - mu * mu;
        float  sc   = (float)((double)gamma2[t] / sqrt(var + 1e-5));
        g_scale2[t] = sc;
        g_shift2[t] = beta2[t] - (float)mu * sc;
    }
    __syncthreads();

    __shared__ float v[64];
    if (t < 64) {
        int      o   = t & 3;
        unsigned e   = g.pool[t];
        float    val = (neg >> o & 1) ? fdec(~e) : fdec(e + REBASE);
        v[t] = (e == 0u) ? 0.0f : fmaf(val, g_scale2[o], g_shift2[o]);
    }
    __syncthreads();
    if (t < 128) {
        int w = t >> 5, l = t & 31;
        float p = v[l] * fcw[w * 64 + l] + v[l + 32] * fcw[w * 64 + l + 32];
#pragma unroll
        for (int o = 16; o; o >>= 1) p += __shfl_down_sync(~0u, p, o);
        if (l == 0) out[w] = p;
    }
}

// ---------------- host launcher (graph-capturable) ---------------------------
extern "C" void kernel_launch(void* const* d_in, const int* in_sizes, int n_in,
                              void* d_out, int out_size) {
    const float* x      = (const float*)d_in[0];
    const void*  eidx   = d_in[1];
    const float* attr   = (const float*)d_in[2];
    const float* pos    = (const float*)d_in[3];
    const float* W1     = (const float*)d_in[4];
    const float* W2     = (const float*)d_in[5];
    const float* gamma1 = (const float*)d_in[6];
    const float* beta1  = (const float*)d_in[7];
    const float* gamma2 = (const float*)d_in[8];
    const float* beta2  = (const float*)d_in[9];
    const float* fcw    = (const float*)d_in[10];
    float*       out    = (float*)d_out;

    int N = in_sizes[0];        // x is [N,1]
    int E = in_sizes[2] / 3;    // edge_attr is [E,3]

    void* pg;
    cudaGetSymbolAddress(&pg, g);
    cudaMemsetAsync(pg, 0, sizeof(ScratchT));

    int ebl  = (E + 511) / 512;    // 2 edges/thread
    int nbl4 = (N + 1023) / 1024;  // 4 nodes/thread

    k_conv1<<<ebl, 256>>>(x, eidx, attr, W1, E);
    k_finish1<<<nbl4, 256>>>(gamma1, beta1, N);
    k_conv2<<<ebl, 256>>>(attr, W2, E);
    k_finish2<<<nbl4, 256>>>(pos, gamma2, beta2, fcw, out, N);
}

// round 9
// speedup vs baseline: 1.0627x; 1.0627x over previous
#include <cuda_runtime.h>
#include <math.h>
#include <stdint.h>

#define NMAX 262144
#define NBANK 16
#define BSTRIDE 32   // doubles per bank (256B stride: no L2 hash pair-collide)

// ---------------- scratch (device globals; single zero-memset) ---------------
struct ScratchT {
    float    h1[4 * NMAX];            // conv1 accum: h0, h1, cnt, pad
    float    h2[4 * NMAX];            // conv2 accum: 4 channels
    double   stats1[NBANK * BSTRIDE]; // banked: [b]: s0,s1,sq0,sq1
    double   stats2[NBANK * BSTRIDE]; // banked: [b]: s0..s3, sq0..sq3
    unsigned done1, done2;            // last-block counters
    unsigned pool[64];                // sign-aware ordered-uint, 0 == empty
};
__device__ ScratchT g;
__device__ float    g_h1e[2 * NMAX];  // elu(mean(h1)) packed float2
__device__ float    g_inv[NMAX];      // 1 / max(cnt,1)
__device__ float    g_scale1[2], g_shift1[2];
__device__ float    g_scale2[4], g_shift2[4];

// ordered-uint encoding: unsigned compare == float compare
__device__ __forceinline__ unsigned fenc(float f) {
    unsigned u = __float_as_uint(f);
    return (u & 0x80000000u) ? ~u : (u | 0x80000000u);
}
__device__ __forceinline__ float fdec(unsigned u) {
    return (u & 0x80000000u) ? __uint_as_float(u & 0x7FFFFFFFu)
                             : __uint_as_float(~u);
}
#define REBASE 0x007FFFFFu   // fenc(-inf): re-base so 0 marks "empty"

// ---------------- trilinear basis weights (pseudo in [0,1): lo==0) -----------
__device__ __forceinline__ void basis8(float f0, float f1, float f2, float* w) {
    float gr0 = 1.f - f0, gr1 = 1.f - f1, gr2 = 1.f - f2;
    float a00 = gr0 * gr1, a10 = f0 * gr1, a01 = gr0 * f1, a11 = f0 * f1;
    w[0] = a00 * gr2; w[1] = a10 * gr2; w[2] = a01 * gr2; w[3] = a11 * gr2;
    w[4] = a00 * f2;  w[5] = a10 * f2;  w[6] = a01 * f2;  w[7] = a11 * f2;
}

// per-block idx-dtype sniff: odd 32-bit words all zero over 8 samples => int64
__device__ __forceinline__ int sniff64(const unsigned* w, int base, int E) {
    unsigned orv = 0;
#pragma unroll
    for (int i = 0; i < 8; i++) {
        int e = base + i;
        if (e < E) orv |= w[2 * e + 1];
    }
    return orv == 0u;
}

// paired index load for edges (e, e+1), e even
__device__ __forceinline__ void load_edge2(const void* eidx, int e, int E, int is64,
                                           int& sA, int& dA, int& sB, int& dB) {
    if (is64) {
        const longlong2* p = (const longlong2*)eidx;
        longlong2 s = __ldg(&p[e >> 1]);
        longlong2 d = __ldg(&p[(size_t)(E >> 1) + (e >> 1)]);
        sA = (int)s.x; sB = (int)s.y; dA = (int)d.x; dB = (int)d.y;
    } else {
        const int2* p = (const int2*)eidx;
        int2 s = __ldg(&p[e >> 1]);
        int2 d = __ldg(&p[(E >> 1) + (e >> 1)]);
        sA = s.x; sB = s.y; dA = d.x; dB = d.y;
    }
}
__device__ __forceinline__ void load_edge1(const void* eidx, int e, int E, int is64,
                                           int& src, int& dst) {
    if (is64) {
        const long long* p = (const long long*)eidx;
        src = (int)__ldg(&p[e]);
        dst = (int)__ldg(&p[(size_t)E + e]);
    } else {
        const int* p = (const int*)eidx;
        src = __ldg(&p[e]);
        dst = __ldg(&p[E + e]);
    }
}

// stage 512 edges' attr (1536 floats) into smem via coalesced float4 loads
__device__ __forceinline__ void stage_attr512(const float* __restrict__ attr,
                                              int base, int nEdge, float* sAttr) {
    int t = threadIdx.x;
    if (nEdge == 512) {
        const float4* a4 = (const float4*)attr;
        int g0 = (3 * base) >> 2;
#pragma unroll
        for (int i = 0; i < 2; i++) {
            int k = t + 256 * i;
            if (k < 384) *(float4*)&sAttr[4 * k] = __ldg(&a4[g0 + k]);
        }
    } else {
        for (int i = t; i < 3 * nEdge; i += 256)
            sAttr[i] = __ldg(&attr[3 * base + i]);
    }
    __syncthreads();
}

// read edge-pair attr via 3x LDS.64 (pair t -> float2 elems 3t, 3t+1, 3t+2)
__device__ __forceinline__ void pair_attr(const float* sAttr, int t,
                                          float* fA, float* fB) {
    const float2* s2 = (const float2*)sAttr;
    float2 p0 = s2[3 * t], p1 = s2[3 * t + 1], p2 = s2[3 * t + 2];
    fA[0] = p0.x; fA[1] = p0.y; fA[2] = p1.x;
    fB[0] = p1.y; fB[1] = p2.x; fB[2] = p2.y;
}

// ---------------- conv1: x[N,1] x W1 -> red.v4 (h0,h1,cnt,0), 2 edges/thr ----
__global__ void __launch_bounds__(256) k_conv1(
        const float* __restrict__ x, const void* __restrict__ eidx,
        const float* __restrict__ attr, const float* __restrict__ W1, int E) {
    __shared__ float2 sW[8];
    __shared__ __align__(16) float sAttr[1536];
    __shared__ int    sI64;
    int t = threadIdx.x;
    int base = blockIdx.x * 512;
    if (t < 8) sW[t] = ((const float2*)W1)[t];
    if (t == 0) sI64 = sniff64((const unsigned*)eidx, base, E);
    int nEdge = min(512, E - base);
    stage_attr512(attr, base, nEdge, sAttr);

    int le = 2 * t;
    if (le >= nEdge) return;
    int e = base + le;

    if (le + 1 < nEdge) {
        int sA, dA, sB, dB;
        load_edge2(eidx, e, E, sI64, sA, dA, sB, dB);
        float xA = __ldg(&x[sA]);
        float xB = __ldg(&x[sB]);
        float fA[3], fB[3], w[8];
        pair_attr(sAttr, t, fA, fB);
        basis8(fA[0], fA[1], fA[2], w);
        float a0 = 0.f, a1 = 0.f;
#pragma unroll
        for (int b = 0; b < 8; b++) { float2 W = sW[b]; a0 = fmaf(w[b], W.x, a0); a1 = fmaf(w[b], W.y, a1); }
        a0 *= xA; a1 *= xA;
        asm volatile("red.global.add.v4.f32 [%0], {%1, %2, %3, %4};"
                     :: "l"(&g.h1[4 * dA]), "f"(a0), "f"(a1), "f"(1.0f), "f"(0.0f) : "memory");
        basis8(fB[0], fB[1], fB[2], w);
        float b0 = 0.f, b1 = 0.f;
#pragma unroll
        for (int b = 0; b < 8; b++) { float2 W = sW[b]; b0 = fmaf(w[b], W.x, b0); b1 = fmaf(w[b], W.y, b1); }
        b0 *= xB; b1 *= xB;
        asm volatile("red.global.add.v4.f32 [%0], {%1, %2, %3, %4};"
                     :: "l"(&g.h1[4 * dB]), "f"(b0), "f"(b1), "f"(1.0f), "f"(0.0f) : "memory");
    } else {
        int src, dst;
        load_edge1(eidx, e, E, sI64, src, dst);
        float w[8];
        basis8(sAttr[3*le], sAttr[3*le+1], sAttr[3*le+2], w);
        float a0 = 0.f, a1 = 0.f;
#pragma unroll
        for (int b = 0; b < 8; b++) { float2 W = sW[b]; a0 = fmaf(w[b], W.x, a0); a1 = fmaf(w[b], W.y, a1); }
        float xs = __ldg(&x[src]);
        a0 *= xs; a1 *= xs;
        asm volatile("red.global.add.v4.f32 [%0], {%1, %2, %3, %4};"
                     :: "l"(&g.h1[4 * dst]), "f"(a0), "f"(a1), "f"(1.0f), "f"(0.0f) : "memory");
    }
}

// ---------------- finish1: 4 nodes/thread, mean->ELU->store, BN1 stats -------
__global__ void __launch_bounds__(256) k_finish1(
        const float* __restrict__ gamma1, const float* __restrict__ beta1, int N) {
    __shared__ float wsum[8][4];
    int t = threadIdx.x;
    int base = blockIdx.x * 1024;
    float s0 = 0.f, s1 = 0.f, s2 = 0.f, s3 = 0.f;
#pragma unroll
    for (int k = 0; k < 4; k++) {
        int n = base + t + 256 * k;
        if (n < N) {
            float4 h  = *(const float4*)&g.h1[4 * n];
            float inv = 1.0f / fmaxf(h.z, 1.0f);
            g_inv[n] = inv;
            float a = h.x * inv, b = h.y * inv;
            a = (a > 0.f) ? a : expm1f(a);
            b = (b > 0.f) ? b : expm1f(b);
            *(float2*)&g_h1e[2 * n] = make_float2(a, b);
            s0 += a; s1 += b; s2 += a * a; s3 += b * b;
        }
    }
#pragma unroll
    for (int o = 16; o; o >>= 1) {
        s0 += __shfl_down_sync(~0u, s0, o);
        s1 += __shfl_down_sync(~0u, s1, o);
        s2 += __shfl_down_sync(~0u, s2, o);
        s3 += __shfl_down_sync(~0u, s3, o);
    }
    if ((t & 31) == 0) {
        int wid = t >> 5;
        wsum[wid][0] = s0; wsum[wid][1] = s1; wsum[wid][2] = s2; wsum[wid][3] = s3;
    }
    __syncthreads();
    if (t < 4) {
        double acc = 0.0;
#pragma unroll
        for (int w = 0; w < 8; w++) acc += (double)wsum[w][t];
        atomicAdd(&g.stats1[(blockIdx.x & (NBANK - 1)) * BSTRIDE + t], acc);
    }
    __shared__ int last;
    __syncthreads();
    if (t == 0) {
        __threadfence();
        last = (atomicAdd(&g.done1, 1u) == gridDim.x - 1);
    }
    __syncthreads();
    if (last && t < 2) {
        __threadfence();
        double sum = 0.0, sumsq = 0.0;
#pragma unroll
        for (int bk = 0; bk < NBANK; bk++) {
            sum   += g.stats1[bk * BSTRIDE + t];
            sumsq += g.stats1[bk * BSTRIDE + 2 + t];
        }
        double invN = 1.0 / (double)N;
        double mu   = sum * invN;
        double var  = sumsq * invN - mu * mu;
        float  sc   = (float)((double)gamma1[t] / sqrt(var + 1e-5));
        g_scale1[t] = sc;
        g_shift1[t] = beta1[t] - (float)mu * sc;
    }
}

// ---------------- conv2: BN1(h1e)[N,2] x W2 -> red.v4 [N,4], 2 edges/thr -----
__global__ void __launch_bounds__(256) k_conv2(
        const void* __restrict__ eidx, const float* __restrict__ attr,
        const float* __restrict__ W2, int E) {
    __shared__ float4 sW[16];     // sW[2b]=W2[b][0][:], sW[2b+1]=W2[b][1][:]
    __shared__ __align__(16) float sAttr[1536];
    __shared__ float  sSc[2], sSh[2];
    __shared__ int    sI64;
    int t = threadIdx.x;
    int base = blockIdx.x * 512;
    if (t < 16) sW[t] = ((const float4*)W2)[t];
    if (t < 2)  { sSc[t] = g_scale1[t]; sSh[t] = g_shift1[t]; }
    if (t == 0) sI64 = sniff64((const unsigned*)eidx, base, E);
    int nEdge = min(512, E - base);
    stage_attr512(attr, base, nEdge, sAttr);

    int le = 2 * t;
    if (le >= nEdge) return;
    int e = base + le;

    if (le + 1 < nEdge) {
        int sA, dA, sB, dB;
        load_edge2(eidx, e, E, sI64, sA, dA, sB, dB);
        float2 hA = *(const float2*)&g_h1e[2 * sA];   // both gathers in flight
        float2 hB = *(const float2*)&g_h1e[2 * sB];
        float fA[3], fB[3], w[8];
        pair_attr(sAttr, t, fA, fB);
#pragma unroll
        for (int j = 0; j < 2; j++) {
            float2 hv = j ? hB : hA;
            int    d  = j ? dB : dA;
            const float* f = j ? fB : fA;
            float h0 = fmaf(hv.x, sSc[0], sSh[0]);
            float h1 = fmaf(hv.y, sSc[1], sSh[1]);
            basis8(f[0], f[1], f[2], w);
            float acc0 = 0.f, acc1 = 0.f, acc2 = 0.f, acc3 = 0.f;
#pragma unroll
            for (int b = 0; b < 8; b++) {
                float4 A = sW[2 * b];
                float4 B = sW[2 * b + 1];
                float wb = w[b];
                acc0 = fmaf(wb, fmaf(h1, B.x, h0 * A.x), acc0);
                acc1 = fmaf(wb, fmaf(h1, B.y, h0 * A.y), acc1);
                acc2 = fmaf(wb, fmaf(h1, B.z, h0 * A.z), acc2);
                acc3 = fmaf(wb, fmaf(h1, B.w, h0 * A.w), acc3);
            }
            asm volatile("red.global.add.v4.f32 [%0], {%1, %2, %3, %4};"
                         :: "l"(&g.h2[4 * d]), "f"(acc0), "f"(acc1), "f"(acc2), "f"(acc3)
                         : "memory");
        }
    } else {
        int src, dst;
        load_edge1(eidx, e, E, sI64, src, dst);
        float2 hv = *(const float2*)&g_h1e[2 * src];
        float h0 = fmaf(hv.x, sSc[0], sSh[0]);
        float h1 = fmaf(hv.y, sSc[1], sSh[1]);
        float w[8];
        basis8(sAttr[3*le], sAttr[3*le+1], sAttr[3*le+2], w);
        float acc0 = 0.f, acc1 = 0.f, acc2 = 0.f, acc3 = 0.f;
#pragma unroll
        for (int b = 0; b < 8; b++) {
            float4 A = sW[2 * b];
            float4 B = sW[2 * b + 1];
            float wb = w[b];
            acc0 = fmaf(wb, fmaf(h1, B.x, h0 * A.x), acc0);
            acc1 = fmaf(wb, fmaf(h1, B.y, h0 * A.y), acc1);
            acc2 = fmaf(wb, fmaf(h1, B.z, h0 * A.z), acc2);
            acc3 = fmaf(wb, fmaf(h1, B.w, h0 * A.w), acc3);
        }
        asm volatile("red.global.add.v4.f32 [%0], {%1, %2, %3, %4};"
                     :: "l"(&g.h2[4 * dst]), "f"(acc0), "f"(acc1), "f"(acc2), "f"(acc3)
                     : "memory");
    }
}

// -- finish2: 4 nodes/thread; mean, BN2 stats+params, sign-aware pool, fc -----
__global__ void __launch_bounds__(256) k_finish2(
        const float* __restrict__ pos,
        const float* __restrict__ gamma2, const float* __restrict__ beta2,
        const float* __restrict__ fcw, float* __restrict__ out, int N) {
    __shared__ unsigned spool[64];
    __shared__ float    wsum[8][8];
    __shared__ unsigned sNeg;
    int t = threadIdx.x;
    if (t < 64) spool[t] = 0u;
    if (t == 0) {
        unsigned mk = 0;
#pragma unroll
        for (int o = 0; o < 4; o++)
            if (__ldg(&gamma2[o]) < 0.f) mk |= 1u << o;
        sNeg = mk;
    }
    __syncthreads();
    unsigned neg = sNeg;

    int base = blockIdx.x * 1024;
    float s[8] = {0.f,0.f,0.f,0.f,0.f,0.f,0.f,0.f};
#pragma unroll
    for (int k = 0; k < 4; k++) {
        int n = base + t + 256 * k;
        if (n < N) {
            float4 h  = *(const float4*)&g.h2[4 * n];
            float inv = g_inv[n];
            float m0 = h.x * inv, m1 = h.y * inv, m2 = h.z * inv, m3 = h.w * inv;
            float2 p = *(const float2*)&pos[2 * n];
            int cx = min(max((int)floorf(p.x * 0.04f), 0), 3);
            int cy = min(max((int)floorf(p.y * 0.04f), 0), 3);
            int cl = 4 * (cx + 4 * cy);
            unsigned e0 = fenc(m0), e1 = fenc(m1), e2 = fenc(m2), e3 = fenc(m3);
            atomicMax(&spool[cl + 0], (neg & 1u) ? ~e0 : (e0 - REBASE));
            atomicMax(&spool[cl + 1], (neg & 2u) ? ~e1 : (e1 - REBASE));
            atomicMax(&spool[cl + 2], (neg & 4u) ? ~e2 : (e2 - REBASE));
            atomicMax(&spool[cl + 3], (neg & 8u) ? ~e3 : (e3 - REBASE));
            s[0] += m0; s[1] += m1; s[2] += m2; s[3] += m3;
            s[4] += m0 * m0; s[5] += m1 * m1; s[6] += m2 * m2; s[7] += m3 * m3;
        }
    }
#pragma unroll
    for (int o = 16; o; o >>= 1)
#pragma unroll
        for (int k = 0; k < 8; k++) s[k] += __shfl_down_sync(~0u, s[k], o);
    if ((t & 31) == 0) {
        int wid = t >> 5;
#pragma unroll
        for (int k = 0; k < 8; k++) wsum[wid][k] = s[k];
    }
    __syncthreads();
    if (t < 8) {
        double acc = 0.0;
#pragma unroll
        for (int w = 0; w < 8; w++) acc += (double)wsum[w][t];
        atomicAdd(&g.stats2[(blockIdx.x & (NBANK - 1)) * BSTRIDE + t], acc);
    }
    if (t < 64 && spool[t]) atomicMax(&g.pool[t], spool[t]);
    __shared__ int last;
    __syncthreads();
    if (t == 0) {
        __threadfence();
        last = (atomicAdd(&g.done2, 1u) == gridDim.x - 1);
    }
    __syncthreads();
    if (!last) return;

    if (t < 4) {
        __threadfence();
        double sum = 0.0, sumsq = 0.0;
#pragma unroll
        for (int bk = 0; bk < NBANK; bk++) {
            sum   += g.stats2[bk * BSTRIDE + t];
            sumsq += g.stats2[bk * BSTRIDE + 4 + t];
        }
        double invN = 1.0 / (double)N;
        double mu   = sum * invN;
        double var  = sumsq * invN - mu * mu;
        float  sc   = (float)((double)gamma2[t] / sqrt(var + 1e-5));
        g_scale2[t] = sc;
        g_shift2[t] = beta2[t] - (float)mu * sc;
    }
    __syncthreads();

    __shared__ float v[64];
    if (t < 64) {
        int      o   = t & 3;
        unsigned e   = g.pool[t];
        float    val = (neg >> o & 1) ? fdec(~e) : fdec(e + REBASE);
        v[t] = (e == 0u) ? 0.0f : fmaf(val, g_scale2[o], g_shift2[o]);
    }
    __syncthreads();
    if (t < 128) {
        int w = t >> 5, l = t & 31;
        float p = v[l] * fcw[w * 64 + l] + v[l + 32] * fcw[w * 64 + l + 32];
#pragma unroll
        for (int o = 16; o; o >>= 1) p += __shfl_down_sync(~0u, p, o);
        if (l == 0) out[w] = p;
    }
}

// ---------------- host launcher (graph-capturable) ---------------------------
extern "C" void kernel_launch(void* const* d_in, const int* in_sizes, int n_in,
                              void* d_out, int out_size) {
    const float* x      = (const float*)d_in[0];
    const void*  eidx   = d_in[1];
    const float* attr   = (const float*)d_in[2];
    const float* pos    = (const float*)d_in[3];
    const float* W1     = (const float*)d_in[4];
    const float* W2     = (const float*)d_in[5];
    const float* gamma1 = (const float*)d_in[6];
    const float* beta1  = (const float*)d_in[7];
    const float* gamma2 = (const float*)d_in[8];
    const float* beta2  = (const float*)d_in[9];
    const float* fcw    = (const float*)d_in[10];
    float*       out    = (float*)d_out;

    int N = in_sizes[0];        // x is [N,1]
    int E = in_sizes[2] / 3;    // edge_attr is [E,3]

    void* pg;
    cudaGetSymbolAddress(&pg, g);
    cudaMemsetAsync(pg, 0, sizeof(ScratchT));

    int ebl  = (E + 511) / 512;    // 2 edges/thread
    int nbl4 = (N + 1023) / 1024;  // 4 nodes/thread

    k_conv1<<<ebl, 256>>>(x, eidx, attr, W1, E);
    k_finish1<<<nbl4, 256>>>(gamma1, beta1, N);
    k_conv2<<<ebl, 256>>>(eidx, attr, W2, E);
    k_finish2<<<nbl4, 256>>>(pos, gamma2, beta2, fcw, out, N);
}